// round 13
// baseline (speedup 1.0000x reference)
#include <cuda_runtime.h>
#include <cuda_fp16.h>

// Problem constants
#define H_ 128
#define W_ 128
#define C_ 32
#define XP_ 64                       // x-pair count
#define NPIX_ (8 * 11 * 128 * 128)   // 1,441,792 pixels
#define PPB_ 256                     // pixels per block
#define NBLOCKS_ (NPIX_ / PPB_)      // 5632

// Parity-duplicated interleaved fp16 source:
//   g_src16[parity][y][xp][c] = half2{ v(y, 2*xp+parity, c), v(y, 2*xp+parity+1, c) }
// One (parity,y,xp) block = 32 half2 = 128 B, 128B-aligned.
__device__ __align__(128) __half2 g_src16[2 * H_ * XP_ * C_];  // 2 MB

__global__ void __launch_bounds__(256) convert_kernel(const float* __restrict__ src)
{
    int idx = blockIdx.x * 256 + threadIdx.x;   // 262144 threads
    int c  = idx & 31;
    int xp = (idx >> 5) & 63;
    int y  = idx >> 11;

    int x0 = 2 * xp;
    const float* row = src + (y << 12) + c;     // (y, x, c): x stride 32 floats
    float v0 = __ldg(row + (x0 << 5));
    float v1 = __ldg(row + ((x0 + 1) << 5));
    int x2 = min(x0 + 2, 127);                  // clamp; (parity=1, xp=63) never read
    float v2 = __ldg(row + (x2 << 5));

    // copy parity 0: pair (2xp, 2xp+1); parity 1: pair (2xp+1, 2xp+2)
    g_src16[idx] = __floats2half2_rn(v0, v1);
    g_src16[(H_ * XP_ * C_) + idx] = __floats2half2_rn(v1, v2);
}

// Per-pixel packed params (16 B):
//   .x = byte offset of the (parity,y=by,xp) block in g_src16 (row y1 = +8192 B)
//   .y = w00 | (w01 << 16)   (u16 fixed-point, x65535)
//   .z = w10 | (w11 << 16)
__global__ void __launch_bounds__(256, 5) deform_kernel(
    const float* __restrict__ mot,   // (NPIX, 2)
    float* __restrict__ out)         // (NPIX, C)
{
    __shared__ int4 s_p[PPB_];

    const int t = threadIdx.x;
    const int blockPix = blockIdx.x * PPB_;

    // ---- Phase 1: each thread computes params for one pixel ----
    {
        const int pix = blockPix + t;
        float2 g = __ldg(((const float2*)mot) + pix);
        float gx = fmaf(g.x, 64.0f, 63.5f);   // (g+1)*64 - 0.5
        float gy = fmaf(g.y, 64.0f, 63.5f);

        float xf = floorf(gx);
        float yf = floorf(gy);
        float fx = gx - xf;      // 'w'
        float fy = gy - yf;      // 'n'
        float ex = 1.0f - fx;    // 'e'
        float sy = 1.0f - fy;    // 's'

        int x0 = (int)xf;
        int y0 = (int)yf;

        bool mx0 = (unsigned)x0 < 128u;
        bool mx1 = (unsigned)(x0 + 1) < 128u;
        bool my0 = (unsigned)y0 < 128u;
        bool my1 = (unsigned)(y0 + 1) < 128u;

        // base clamped so the whole 2x2 footprint is in-bounds
        int bx = min(max(x0, 0), 126);
        int by = min(max(y0, 0), 126);

        // x-axis weights mapped onto span [bx, bx+1]
        float ax_lo, ax_hi;
        if (mx0 & mx1)      { ax_lo = ex;   ax_hi = fx;   }
        else if (mx1)       { ax_lo = fx;   ax_hi = 0.0f; }
        else if (mx0)       { ax_lo = 0.0f; ax_hi = ex;   }
        else                { ax_lo = 0.0f; ax_hi = 0.0f; }

        float ay_lo, ay_hi;
        if (my0 & my1)      { ay_lo = sy;   ay_hi = fy;   }
        else if (my1)       { ay_lo = fy;   ay_hi = 0.0f; }
        else if (my0)       { ay_lo = 0.0f; ay_hi = sy;   }
        else                { ay_lo = 0.0f; ay_hi = 0.0f; }

        unsigned q00 = __float2uint_rn(ay_lo * ax_lo * 65535.0f);
        unsigned q01 = __float2uint_rn(ay_lo * ax_hi * 65535.0f);
        unsigned q10 = __float2uint_rn(ay_hi * ax_lo * 65535.0f);
        unsigned q11 = __float2uint_rn(ay_hi * ax_hi * 65535.0f);

        int parity = bx & 1;
        int xp = bx >> 1;

        int4 prm;
        // byte offset of block (parity, by, xp): ((parity*128 + by)*64 + xp) * 128
        prm.x = (((parity << 7) + by) * 64 + xp) << 7;
        prm.y = (int)(q00 | (q01 << 16));
        prm.z = (int)(q10 | (q11 << 16));
        prm.w = 0;
        s_p[t] = prm;
    }
    __syncthreads();

    // ---- Phase 2: warp = 1 pixel/iter, 32 lanes = 32 channels.
    //      Each row load: warp-uniform 128 B line (both x corners) = 1 wavefront.
    const int lane = t & 31;
    const int warp = t >> 5;

    const int4* __restrict__ pp = s_p + (warp << 5);
    const char* __restrict__ sb = (const char*)g_src16 + (lane << 2);
    char* __restrict__ outB = (char*)out
        + ((blockPix + (warp << 5)) << 7) + (lane << 2);

    #pragma unroll 4
    for (int p = 0; p < 32; ++p) {
        int4 prm = pp[p];                       // LDS.128, uniform bcast

        const __half2* a = (const __half2*)(sb + prm.x);
        __half2 h0 = __ldg(a);                  // row y0: {v_lo, v_hi}
        __half2 h1 = __ldg(a + 2048);           // row y1: +8192 B
        float2 f0 = __half22float2(h0);
        float2 f1 = __half22float2(h1);

        unsigned pa = (unsigned)prm.y;
        unsigned pb = (unsigned)prm.z;
        float w00 = (float)(pa & 0xFFFFu);
        float w01 = (float)(pa >> 16);
        float w10 = (float)(pb & 0xFFFFu);
        float w11 = (float)(pb >> 16);

        float r = fmaf(w00, f0.x, fmaf(w01, f0.y, fmaf(w10, f1.x, w11 * f1.y)));
        *(float*)(outB + (p << 7)) = r * (1.0f / 65535.0f);   // STG.32, 128 B/warp
    }
}

extern "C" void kernel_launch(void* const* d_in, const int* in_sizes, int n_in,
                              void* d_out, int out_size)
{
    const float* src = (const float*)d_in[0];   // source (1,H,W,C)
    const float* mot = (const float*)d_in[1];   // motions (BS,NKP,H,W,2)
    float* out = (float*)d_out;

    convert_kernel<<<(2 * H_ * XP_ * C_) / 256 / 2, 256>>>(src);  // 1024 blocks
    deform_kernel<<<NBLOCKS_, 256>>>(mot, out);
}

// round 14
// speedup vs baseline: 1.3728x; 1.3728x over previous
#include <cuda_runtime.h>
#include <cuda_fp16.h>

// Problem constants
#define H_ 128
#define W_ 128
#define C_ 32
#define XP_ 64                       // x-pair count
#define NPIX_ (8 * 11 * 128 * 128)   // 1,441,792 pixels
#define PPB_ 256                     // pixels per block
#define NBLOCKS_ (NPIX_ / PPB_)      // 5632

// Parity-duplicated interleaved fp16 source:
//   g_src16[parity][y][xp][c] = half2{ v(y, 2*xp+parity, c), v(y, 2*xp+parity+1, c) }
// One (parity,y,xp) block = 32 half2 = 128 B, 128B-aligned.
__device__ __align__(128) __half2 g_src16[2 * H_ * XP_ * C_];  // 2 MB

__global__ void __launch_bounds__(256) convert_kernel(const float* __restrict__ src)
{
    int idx = blockIdx.x * 256 + threadIdx.x;   // 262144 threads
    int c  = idx & 31;
    int xp = (idx >> 5) & 63;
    int y  = idx >> 11;

    int x0 = 2 * xp;
    const float* row = src + (y << 12) + c;     // (y, x, c): x stride 32 floats
    float v0 = __ldg(row + (x0 << 5));
    float v1 = __ldg(row + ((x0 + 1) << 5));
    int x2 = min(x0 + 2, 127);                  // clamp; (parity=1, xp=63) never read
    float v2 = __ldg(row + (x2 << 5));

    // copy parity 0: pair (2xp, 2xp+1); parity 1: pair (2xp+1, 2xp+2)
    g_src16[idx] = __floats2half2_rn(v0, v1);
    g_src16[(H_ * XP_ * C_) + idx] = __floats2half2_rn(v1, v2);
}

// Per-pixel packed params (16 B):
//   .x = byte offset of the (parity,y=by,xp) block in g_src16 (row y1 = +8192 B)
//   .y = half2(w00, w01)  bits
//   .z = half2(w10, w11)  bits
__global__ void __launch_bounds__(256, 5) deform_kernel(
    const float* __restrict__ mot,   // (NPIX, 2)
    float* __restrict__ out)         // (NPIX, C)
{
    __shared__ int4 s_p[PPB_];

    const int t = threadIdx.x;
    const int blockPix = blockIdx.x * PPB_;

    // ---- Phase 1: each thread computes params for one pixel ----
    {
        const int pix = blockPix + t;
        float2 g = __ldg(((const float2*)mot) + pix);
        float gx = fmaf(g.x, 64.0f, 63.5f);   // (g+1)*64 - 0.5
        float gy = fmaf(g.y, 64.0f, 63.5f);

        float xf = floorf(gx);
        float yf = floorf(gy);
        float fx = gx - xf;      // 'w'
        float fy = gy - yf;      // 'n'
        float ex = 1.0f - fx;    // 'e'
        float sy = 1.0f - fy;    // 's'

        int x0 = (int)xf;
        int y0 = (int)yf;

        bool mx0 = (unsigned)x0 < 128u;
        bool mx1 = (unsigned)(x0 + 1) < 128u;
        bool my0 = (unsigned)y0 < 128u;
        bool my1 = (unsigned)(y0 + 1) < 128u;

        // base clamped so the whole 2x2 footprint is in-bounds
        int bx = min(max(x0, 0), 126);
        int by = min(max(y0, 0), 126);

        // x-axis weights mapped onto span [bx, bx+1]
        float ax_lo, ax_hi;
        if (mx0 & mx1)      { ax_lo = ex;   ax_hi = fx;   }
        else if (mx1)       { ax_lo = fx;   ax_hi = 0.0f; }
        else if (mx0)       { ax_lo = 0.0f; ax_hi = ex;   }
        else                { ax_lo = 0.0f; ax_hi = 0.0f; }

        float ay_lo, ay_hi;
        if (my0 & my1)      { ay_lo = sy;   ay_hi = fy;   }
        else if (my1)       { ay_lo = fy;   ay_hi = 0.0f; }
        else if (my0)       { ay_lo = 0.0f; ay_hi = sy;   }
        else                { ay_lo = 0.0f; ay_hi = 0.0f; }

        __half2 hA = __floats2half2_rn(ay_lo * ax_lo, ay_lo * ax_hi); // w00, w01
        __half2 hB = __floats2half2_rn(ay_hi * ax_lo, ay_hi * ax_hi); // w10, w11

        int parity = bx & 1;
        int xp = bx >> 1;

        int4 prm;
        // byte offset of block (parity, by, xp): ((parity*128 + by)*64 + xp) * 128
        prm.x = (((parity << 7) + by) * 64 + xp) << 7;
        prm.y = *reinterpret_cast<int*>(&hA);
        prm.z = *reinterpret_cast<int*>(&hB);
        prm.w = 0;
        s_p[t] = prm;
    }
    __syncthreads();

    // ---- Phase 2: 2 pixels per warp-iteration.
    //      lanes 0-15 -> pixel A, lanes 16-31 -> pixel B; lane owns channels 2m,2m+1.
    //      Row gather: LDG.64, each half-warp covers one full 128 B line.
    const int lane = t & 31;
    const int warp = t >> 5;
    const int half = lane >> 4;
    const int m    = lane & 15;

    const int4* __restrict__ pp = s_p + (warp << 5) + half;   // stride 2 pixels
    const char* __restrict__ sb = (const char*)g_src16 + (m << 3);
    char* __restrict__ outB = (char*)out
        + ((blockPix + (warp << 5) + half) << 7) + (m << 3);

    #pragma unroll 4
    for (int it = 0; it < 16; ++it) {
        int4 prm = pp[it << 1];                 // LDS.128, 2 bcast addrs/warp

        const uint2* a = (const uint2*)(sb + prm.x);
        uint2 r0 = __ldg(a);                    // row y0: ch2m, ch2m+1 half2 pairs
        uint2 r1 = __ldg(a + 1024);             // row y1: +8192 B

        float2 wA = __half22float2(*reinterpret_cast<__half2*>(&prm.y));
        float2 wB = __half22float2(*reinterpret_cast<__half2*>(&prm.z));

        float2 c0r0 = __half22float2(*reinterpret_cast<__half2*>(&r0.x));
        float2 c1r0 = __half22float2(*reinterpret_cast<__half2*>(&r0.y));
        float2 c0r1 = __half22float2(*reinterpret_cast<__half2*>(&r1.x));
        float2 c1r1 = __half22float2(*reinterpret_cast<__half2*>(&r1.y));

        float2 o2;
        o2.x = fmaf(wA.x, c0r0.x, fmaf(wA.y, c0r0.y,
               fmaf(wB.x, c0r1.x, wB.y * c0r1.y)));
        o2.y = fmaf(wA.x, c1r0.x, fmaf(wA.y, c1r0.y,
               fmaf(wB.x, c1r1.x, wB.y * c1r1.y)));
        *(float2*)(outB + (it << 8)) = o2;      // STG.64, 2 px = 256 B contig
    }
}

extern "C" void kernel_launch(void* const* d_in, const int* in_sizes, int n_in,
                              void* d_out, int out_size)
{
    const float* src = (const float*)d_in[0];   // source (1,H,W,C)
    const float* mot = (const float*)d_in[1];   // motions (BS,NKP,H,W,2)
    float* out = (float*)d_out;

    convert_kernel<<<(2 * H_ * XP_ * C_) / 256 / 2, 256>>>(src);  // 1024 blocks
    deform_kernel<<<NBLOCKS_, 256>>>(mot, out);
}

// round 15
// speedup vs baseline: 1.3810x; 1.0060x over previous
#include <cuda_runtime.h>
#include <cuda_fp16.h>

// Problem constants
#define H_ 128
#define W_ 128
#define C_ 32
#define XP_ 64                       // x-pair count
#define NPIX_ (8 * 11 * 128 * 128)   // 1,441,792 pixels
#define PPB_ 256                     // pixels per block
#define NBLOCKS_ (NPIX_ / PPB_)      // 5632

// Parity-duplicated interleaved fp16 source:
//   g_src16[parity][y][xp][c] = half2{ v(y, 2*xp+parity, c), v(y, 2*xp+parity+1, c) }
// One (parity,y,xp) block = 32 half2 = 128 B, 128B-aligned.
__device__ __align__(128) __half2 g_src16[2 * H_ * XP_ * C_];  // 2 MB

__global__ void __launch_bounds__(256) convert_kernel(const float* __restrict__ src)
{
    int idx = blockIdx.x * 256 + threadIdx.x;   // 262144 threads
    int c  = idx & 31;
    int xp = (idx >> 5) & 63;
    int y  = idx >> 11;

    int x0 = 2 * xp;
    const float* row = src + (y << 12) + c;     // (y, x, c): x stride 32 floats
    float v0 = __ldg(row + (x0 << 5));
    float v1 = __ldg(row + ((x0 + 1) << 5));
    int x2 = min(x0 + 2, 127);                  // clamp; (parity=1, xp=63) never read
    float v2 = __ldg(row + (x2 << 5));

    // copy parity 0: pair (2xp, 2xp+1); parity 1: pair (2xp+1, 2xp+2)
    g_src16[idx] = __floats2half2_rn(v0, v1);
    g_src16[(H_ * XP_ * C_) + idx] = __floats2half2_rn(v1, v2);
}

// Per-pixel packed params (16 B):
//   .x = byte offset of the (parity,y=by,xp) block in g_src16 (row y1 = +8192 B)
//   .y = half2(w00, w01)  bits
//   .z = half2(w10, w11)  bits
__global__ void __launch_bounds__(256, 6) deform_kernel(
    const float* __restrict__ mot,   // (NPIX, 2)
    float* __restrict__ out)         // (NPIX, C)
{
    __shared__ int4 s_p[PPB_];

    const int t = threadIdx.x;
    const int blockPix = blockIdx.x * PPB_;

    // ---- Phase 1: warp-local. Lane p computes params for pixel p of THIS
    //      warp's own 32-pixel batch; only __syncwarp needed. ----
    {
        const int pix = blockPix + t;            // warp w, lane l -> pixel 32w+l
        float2 g = __ldg(((const float2*)mot) + pix);
        float gx = fmaf(g.x, 64.0f, 63.5f);   // (g+1)*64 - 0.5
        float gy = fmaf(g.y, 64.0f, 63.5f);

        float xf = floorf(gx);
        float yf = floorf(gy);
        float fx = gx - xf;      // 'w'
        float fy = gy - yf;      // 'n'
        float ex = 1.0f - fx;    // 'e'
        float sy = 1.0f - fy;    // 's'

        int x0 = (int)xf;
        int y0 = (int)yf;

        bool mx0 = (unsigned)x0 < 128u;
        bool mx1 = (unsigned)(x0 + 1) < 128u;
        bool my0 = (unsigned)y0 < 128u;
        bool my1 = (unsigned)(y0 + 1) < 128u;

        // base clamped so the whole 2x2 footprint is in-bounds
        int bx = min(max(x0, 0), 126);
        int by = min(max(y0, 0), 126);

        // x-axis weights mapped onto span [bx, bx+1]
        float ax_lo, ax_hi;
        if (mx0 & mx1)      { ax_lo = ex;   ax_hi = fx;   }
        else if (mx1)       { ax_lo = fx;   ax_hi = 0.0f; }
        else if (mx0)       { ax_lo = 0.0f; ax_hi = ex;   }
        else                { ax_lo = 0.0f; ax_hi = 0.0f; }

        float ay_lo, ay_hi;
        if (my0 & my1)      { ay_lo = sy;   ay_hi = fy;   }
        else if (my1)       { ay_lo = fy;   ay_hi = 0.0f; }
        else if (my0)       { ay_lo = 0.0f; ay_hi = sy;   }
        else                { ay_lo = 0.0f; ay_hi = 0.0f; }

        __half2 hA = __floats2half2_rn(ay_lo * ax_lo, ay_lo * ax_hi); // w00, w01
        __half2 hB = __floats2half2_rn(ay_hi * ax_lo, ay_hi * ax_hi); // w10, w11

        int parity = bx & 1;
        int xp = bx >> 1;

        int4 prm;
        // byte offset of block (parity, by, xp): ((parity*128 + by)*64 + xp) * 128
        prm.x = (((parity << 7) + by) * 64 + xp) << 7;
        prm.y = *reinterpret_cast<int*>(&hA);
        prm.z = *reinterpret_cast<int*>(&hB);
        prm.w = 0;
        s_p[t] = prm;
    }
    __syncwarp();

    // ---- Phase 2: 2 pixels per warp-iteration.
    //      lanes 0-15 -> pixel A, lanes 16-31 -> pixel B; lane owns channels 2m,2m+1.
    //      Row gather: LDG.64, each half-warp covers one full 128 B line.
    const int lane = t & 31;
    const int warp = t >> 5;
    const int half = lane >> 4;
    const int m    = lane & 15;

    const int4* __restrict__ pp = s_p + (warp << 5) + half;   // stride 2 pixels
    const char* __restrict__ sb = (const char*)g_src16 + (m << 3);
    char* __restrict__ outB = (char*)out
        + ((blockPix + (warp << 5) + half) << 7) + (m << 3);

    #pragma unroll 4
    for (int it = 0; it < 16; ++it) {
        int4 prm = pp[it << 1];                 // LDS.128, 2 bcast addrs/warp

        const uint2* a = (const uint2*)(sb + prm.x);
        uint2 r0 = __ldg(a);                    // row y0: ch2m, ch2m+1 half2 pairs
        uint2 r1 = __ldg(a + 1024);             // row y1: +8192 B

        float2 wA = __half22float2(*reinterpret_cast<__half2*>(&prm.y));
        float2 wB = __half22float2(*reinterpret_cast<__half2*>(&prm.z));

        float2 c0r0 = __half22float2(*reinterpret_cast<__half2*>(&r0.x));
        float2 c1r0 = __half22float2(*reinterpret_cast<__half2*>(&r0.y));
        float2 c0r1 = __half22float2(*reinterpret_cast<__half2*>(&r1.x));
        float2 c1r1 = __half22float2(*reinterpret_cast<__half2*>(&r1.y));

        float2 o2;
        o2.x = fmaf(wA.x, c0r0.x, fmaf(wA.y, c0r0.y,
               fmaf(wB.x, c0r1.x, wB.y * c0r1.y)));
        o2.y = fmaf(wA.x, c1r0.x, fmaf(wA.y, c1r0.y,
               fmaf(wB.x, c1r1.x, wB.y * c1r1.y)));
        *(float2*)(outB + (it << 8)) = o2;      // STG.64, 2 px = 256 B contig
    }
}

extern "C" void kernel_launch(void* const* d_in, const int* in_sizes, int n_in,
                              void* d_out, int out_size)
{
    const float* src = (const float*)d_in[0];   // source (1,H,W,C)
    const float* mot = (const float*)d_in[1];   // motions (BS,NKP,H,W,2)
    float* out = (float*)d_out;

    convert_kernel<<<(2 * H_ * XP_ * C_) / 256 / 2, 256>>>(src);  // 1024 blocks
    deform_kernel<<<NBLOCKS_, 256>>>(mot, out);
}